// round 16
// baseline (speedup 1.0000x reference)
#include <cuda_runtime.h>
#include <cuda_fp16.h>
#include <math.h>
#include <stdint.h>

// ---------------- problem constants ----------------
#define NB 2
#define CC 256
#define HH 100
#define WW 100
#define NROI 512
#define PP 7
#define SS 4
#define SCALEF 0.0625f
#define TRANS_STDF 0.1f
#define K1 (CC*PP*PP)     // 12544
#define DFC 1024
#define M3 (PP*PP*3)      // 147

// ---------------- scratch (device globals; no allocs allowed) ----------------
__device__ __half g_featTh[NB*HH*WW*CC];  // NHWC features, fp16 (10.2 MB)
__device__ __half g_Xh[NROI*K1];          // pooled features, fp16
__device__ __half g_H1h[NROI*DFC];
__device__ __half g_H2h[NROI*DFC];
__device__ __half g_w1h[DFC*K1];          // fp16 weights (converted per launch)
__device__ __half g_w2h[DFC*DFC];
__device__ __half g_w3h[M3*DFC];
__device__ float  g_part[9*NROI*DFC];     // split-K partials (fp32)

// ======================= small PTX helpers (sm_80+ baseline only) =======================
__device__ __forceinline__ uint32_t smem_u32(const void* p) {
    uint32_t a;
    asm("{ .reg .u64 t; cvta.to.shared.u64 t, %1; cvt.u32.u64 %0, t; }"
        : "=r"(a) : "l"(p));
    return a;
}

__device__ __forceinline__ void cpasync16(uint32_t dst, const void* src, bool pred) {
    int sz = pred ? 16 : 0;
    asm volatile("cp.async.cg.shared.global [%0], [%1], 16, %2;"
                 :: "r"(dst), "l"(src), "r"(sz) : "memory");
}

__device__ __forceinline__ void mma_f16(float c[4], const uint32_t a[4], const uint32_t b[2]) {
    asm volatile(
        "mma.sync.aligned.m16n8k16.row.col.f32.f16.f16.f32 "
        "{%0,%1,%2,%3}, {%4,%5,%6,%7}, {%8,%9}, {%0,%1,%2,%3};"
        : "+f"(c[0]), "+f"(c[1]), "+f"(c[2]), "+f"(c[3])
        : "r"(a[0]), "r"(a[1]), "r"(a[2]), "r"(a[3]), "r"(b[0]), "r"(b[1]));
}

// ---------------- fp32 -> fp16 weight conversion (per launch, deterministic) ----------------
__global__ void __launch_bounds__(256) cvt_half_kernel(const float* __restrict__ src,
                                                       __half* __restrict__ dst, int n4) {
    int i = blockIdx.x * 256 + threadIdx.x;
    if (i >= n4) return;
    float4 v = reinterpret_cast<const float4*>(src)[i];
    __half2 h0 = __floats2half2_rn(v.x, v.y);
    __half2 h1 = __floats2half2_rn(v.z, v.w);
    reinterpret_cast<__half2*>(dst)[i*2]     = h0;
    reinterpret_cast<__half2*>(dst)[i*2 + 1] = h1;
}

// ---------------- NCHW -> NHWC transpose, fp32 -> fp16, half2 writes ----------------
// Block: (32,8). Tile: 64 channels x 32 hw. Writes: each thread stores a half2
// (2 adjacent channels) -> warp writes 128B contiguous.
__global__ void transpose_kernel(const float* __restrict__ feat) {
    __shared__ float tile[64][33];
    int b   = blockIdx.z;
    int hw0 = blockIdx.x * 32;
    int c0  = blockIdx.y * 64;
    int tx = threadIdx.x, ty = threadIdx.y; // (32, 8)
    const float* src = feat + (size_t)b * CC * HH * WW;
    __half* dst = g_featTh + (size_t)b * HH * WW * CC;
    #pragma unroll
    for (int j = 0; j < 64; j += 8) {
        int c  = c0 + ty + j;
        int hw = hw0 + tx;
        tile[ty + j][tx] = (hw < HH*WW) ? src[c * (HH*WW) + hw] : 0.0f;
    }
    __syncthreads();
    #pragma unroll
    for (int jj = 0; jj < 32; jj += 8) {
        int hw = hw0 + ty + jj;
        if (hw < HH*WW) {
            int hl = ty + jj;
            __half2 h = __floats2half2_rn(tile[tx*2][hl], tile[tx*2+1][hl]);
            *reinterpret_cast<__half2*>(dst + (size_t)hw * CC + c0 + tx*2) = h;
        }
    }
}

// ================= fused deformable PSROI pool: one block per ROI =================
// stage 0 (TRANS only): reduce FC3 split-K partials + bias -> om[147] in smem
// stage 1: threads 0..48 compute per-bin COMPACTED cell lists (wt, feat-offset)
// stage 2: 49 bins x 32 channel-octets striped over 512 threads, uint4 fp16 gathers
// stage 3: coalesced write of the 12544 row in (c*49+pp) layout (fp16 or fp32)
#define VPITCH 260
#define MROW 56                 // per-bin meta row: [0]=nnz, then (wt, off) pairs (max 25)
#define FC3_SPLITK 32
#define FUSED_SMEM ((49*VPITCH + 49*MROW + 148) * 4)

template<bool TRANS>
__global__ void __launch_bounds__(512) pool_fused_kernel(const float* __restrict__ rois,
                                                         const float* __restrict__ Part,
                                                         const float* __restrict__ bias3,
                                                         void* __restrict__ dstbuf) {
    extern __shared__ float sg[];
    float* vals  = sg;                          // [49 pp][VPITCH]; doubles as stage-1 scratch
    float* smeta = sg + 49*VPITCH;              // [49 pp][MROW]
    float* som   = sg + 49*VPITCH + 49*MROW;    // [147] offsets+mask logits

    int n   = blockIdx.x;
    int tid = threadIdx.x;

    // ---- stage 0: fold FC3 split-K reduce into this kernel ----
    if (TRANS) {
        if (tid < M3) {
            float s = 0.0f;
            #pragma unroll
            for (int z = 0; z < FC3_SPLITK; z++)
                s += Part[((size_t)z * NROI + n) * 256 + tid];
            som[tid] = s + bias3[tid];
        }
        __syncthreads();
    }

    // ---- stage 1: metadata for 49 bins, compacted ----
    if (tid < 49) {
        int pp = tid;
        int ph = pp / 7, pw = pp % 7;
        float* wg = vals + pp * 36;      // scratch (vals not yet live)
        #pragma unroll
        for (int i = 0; i < 36; i++) wg[i] = 0.0f;

        const float* r = rois + n * 5;
        int b = (int)r[0];
        float rsw = rintf(r[1]) * SCALEF - 0.5f;
        float rsh = rintf(r[2]) * SCALEF - 0.5f;
        float rew = (rintf(r[3]) + 1.0f) * SCALEF - 0.5f;
        float reh = (rintf(r[4]) + 1.0f) * SCALEF - 0.5f;
        float roi_w = fmaxf(rew - rsw, 0.1f);
        float roi_h = fmaxf(reh - rsh, 0.1f);
        float bin_h = roi_h / (float)PP;
        float bin_w = roi_w / (float)PP;
        float sub_h = bin_h / (float)SS;
        float sub_w = bin_w / (float)SS;

        float tx_ = 0.0f, ty_ = 0.0f, mask = 1.0f;
        if (TRANS) {
            int part_h = (int)floorf((float)ph / (float)PP * 7.0f);
            int part_w = (int)floorf((float)pw / (float)PP * 7.0f);
            tx_ = som[0*49 + part_h*7 + part_w] * TRANS_STDF;
            ty_ = som[1*49 + part_h*7 + part_w] * TRANS_STDF;
            float ml = som[2*49 + pp];
            mask = 1.0f / (1.0f + expf(-ml));
        }
        float hstart = (float)ph * bin_h + rsh + ty_ * roi_h;
        float wstart = (float)pw * bin_w + rsw + tx_ * roi_w;

        int horg = (int)floorf(fminf(fmaxf(hstart, 0.0f), (float)(HH-1)));
        int worg = (int)floorf(fminf(fmaxf(wstart, 0.0f), (float)(WW-1)));
        int cnt = 0;
        #pragma unroll
        for (int iy = 0; iy < SS; iy++) {
            float h = hstart + (float)iy * sub_h;
            #pragma unroll
            for (int ix = 0; ix < SS; ix++) {
                float w = wstart + (float)ix * sub_w;
                bool valid = (w >= -0.5f) && (w <= (float)WW - 0.5f) &&
                             (h >= -0.5f) && (h <= (float)HH - 0.5f);
                if (!valid) continue;
                cnt++;
                float hc = fminf(fmaxf(h, 0.0f), (float)(HH-1));
                float wc = fminf(fmaxf(w, 0.0f), (float)(WW-1));
                int h0 = (int)floorf(hc), w0 = (int)floorf(wc);
                int h1 = min(h0 + 1, HH - 1), w1 = min(w0 + 1, WW - 1);
                float lh = hc - (float)h0, lw = wc - (float)w0;
                int r0 = min(max(h0 - horg, 0), 5);
                int r1 = min(max(h1 - horg, 0), 5);
                int c0 = min(max(w0 - worg, 0), 5);
                int c1 = min(max(w1 - worg, 0), 5);
                wg[r0*6 + c0] += (1.0f - lh) * (1.0f - lw);
                wg[r0*6 + c1] += (1.0f - lh) * lw;
                wg[r1*6 + c0] += lh * (1.0f - lw);
                wg[r1*6 + c1] += lh * lw;
            }
        }
        float invc = (cnt > 0) ? (1.0f / (float)cnt) : 0.0f;
        float scale = invc * (TRANS ? mask : 1.0f);
        int bbase = b * HH * WW;
        float* m = smeta + pp * MROW;
        int nnz = 0;
        #pragma unroll
        for (int cell = 0; cell < 36; cell++) {
            float wt = wg[cell];
            if (wt != 0.0f) {
                int y = min(horg + cell / 6, HH - 1);
                int x = min(worg + cell % 6, WW - 1);
                m[1 + 2*nnz] = wt * scale;
                m[2 + 2*nnz] = __int_as_float((bbase + y * WW + x) * CC);
                nnz++;
            }
        }
        m[0] = __int_as_float(nnz);
    }
    __syncthreads();

    // ---- stage 2: gather 49 bins x 32 channel-octets (8 halfs each) ----
    #pragma unroll 1
    for (int t = tid; t < 49 * 32; t += 512) {
        int bin = t >> 5;
        int grp = t & 31;
        const float* m = smeta + bin * MROW;
        int nnz = __float_as_int(m[0]);

        float acc[8];
        #pragma unroll
        for (int j = 0; j < 8; j++) acc[j] = 0.0f;
        #pragma unroll 1
        for (int i = 0; i < nnz; i++) {
            float wt  = m[1 + 2*i];
            int   off = __float_as_int(m[2 + 2*i]);
            uint4 f = *reinterpret_cast<const uint4*>(g_featTh + off + grp * 8);
            const __half2* hp = reinterpret_cast<const __half2*>(&f);
            #pragma unroll
            for (int j = 0; j < 4; j++) {
                float2 v = __half22float2(hp[j]);
                acc[2*j]   += wt * v.x;
                acc[2*j+1] += wt * v.y;
            }
        }
        float* vp = vals + bin * VPITCH + grp * 8;
        #pragma unroll
        for (int j = 0; j < 8; j++) vp[j] = acc[j];
    }
    __syncthreads();

    // ---- stage 3: coalesced output in (c*49+pp) layout (guarded: K1 % 512 != 0) ----
    if (TRANS) {
        float* dst = (float*)dstbuf + (size_t)n * K1;
        #pragma unroll 1
        for (int k = tid; k < K1; k += 512) {
            int c = k / 49, pp = k - c * 49;
            dst[k] = vals[pp * VPITCH + c];
        }
    } else {
        __half* dst = (__half*)dstbuf + (size_t)n * K1;
        #pragma unroll 1
        for (int k = tid; k < K1; k += 512) {
            int c = k / 49, pp = k - c * 49;
            dst[k] = __float2half_rn(vals[pp * VPITCH + c]);
        }
    }
}

// ============ FP16 mma.sync GEMM, split-K, BM=128 x BN=256, 16 warps x 32x64 ============
#define BM 128
#define BN 256
#define BK 32
#define HPITCH 40                 // halfs per smem row (conflict-free frag loads)
#define GSTAGES 4
#define ASZH (BM*HPITCH)
#define BSZH (BN*HPITCH)
#define STGH (ASZH+BSZH)
#define GEMM_SMEM_BYTES (GSTAGES*STGH*2)   // 122880 B

template<int KDIM, int JROWS, int JS, int SPLITK>
__global__ void __launch_bounds__(512) fcmma_kernel(
    const __half* __restrict__ A, const __half* __restrict__ Wt,
    float* __restrict__ Part)
{
    static_assert(KDIM % BK == 0, "K multiple of BK");
    constexpr int KT = KDIM / BK;
    constexpr int CH = (KT + SPLITK - 1) / SPLITK;

    extern __shared__ __half smh[];
    int tid  = threadIdx.x;
    int lane = tid & 31, wid = tid >> 5;   // 16 warps
    int m0 = blockIdx.y * BM, n0 = blockIdx.x * BN;
    int z  = blockIdx.z;
    int t0 = z * CH;
    int ntc = min(KT - t0, CH);

    int g = lane >> 2, tg = lane & 3;
    int wm = (wid & 3) * 32;        // 4 warps along M (32 rows each)
    int wn = (wid >> 2) * 64;       // 4 warps along N (64 cols each)

    float c[2][8][4];
    #pragma unroll
    for (int mt = 0; mt < 2; mt++)
        #pragma unroll
        for (int nt = 0; nt < 8; nt++)
            #pragma unroll
            for (int q = 0; q < 4; q++) c[mt][nt][q] = 0.0f;

    int lrow = tid >> 2;     // 0..127
    int lchk = tid & 3;      // 0..3 (16B = 8-half chunks of a BK row)

    auto load_stage = [&](int s, int t) {
        __half* As = smh + s * STGH;
        __half* Bs = As + ASZH;
        int kg = t * BK + lchk * 8;
        cpasync16(smem_u32(As + lrow * HPITCH + lchk * 8),
                  A + (size_t)(m0 + lrow) * KDIM + kg, true);
        #pragma unroll
        for (int it = 0; it < 2; it++) {
            int r = lrow + it * 128;
            int br = n0 + r;
            bool ok = ((JROWS % BN) == 0) || (br < JROWS);
            cpasync16(smem_u32(Bs + r * HPITCH + lchk * 8),
                      Wt + (size_t)(ok ? br : 0) * KDIM + kg, ok);
        }
    };

    #pragma unroll
    for (int s = 0; s < GSTAGES - 1; s++) {
        if (s < ntc) load_stage(s, t0 + s);
        asm volatile("cp.async.commit_group;" ::: "memory");
    }

    #pragma unroll 1
    for (int i = 0; i < ntc; i++) {
        asm volatile("cp.async.wait_group %0;" :: "n"(GSTAGES - 2) : "memory");
        __syncthreads();

        int tn = i + GSTAGES - 1;
        if (tn < ntc) load_stage(tn % GSTAGES, t0 + tn);
        asm volatile("cp.async.commit_group;" ::: "memory");

        const __half* As = smh + (i % GSTAGES) * STGH;
        const __half* Bs = As + ASZH;
        #pragma unroll
        for (int ks = 0; ks < 2; ks++) {
            int kk = ks * 16;
            uint32_t a[2][4], b[8][2];
            #pragma unroll
            for (int mt = 0; mt < 2; mt++) {
                int m = wm + mt * 16 + g;
                a[mt][0] = *reinterpret_cast<const uint32_t*>(As + m * HPITCH + kk + tg*2);
                a[mt][1] = *reinterpret_cast<const uint32_t*>(As + (m + 8) * HPITCH + kk + tg*2);
                a[mt][2] = *reinterpret_cast<const uint32_t*>(As + m * HPITCH + kk + tg*2 + 8);
                a[mt][3] = *reinterpret_cast<const uint32_t*>(As + (m + 8) * HPITCH + kk + tg*2 + 8);
            }
            #pragma unroll
            for (int nt = 0; nt < 8; nt++) {
                int nn = wn + nt * 8 + g;
                b[nt][0] = *reinterpret_cast<const uint32_t*>(Bs + nn * HPITCH + kk + tg*2);
                b[nt][1] = *reinterpret_cast<const uint32_t*>(Bs + nn * HPITCH + kk + tg*2 + 8);
            }
            #pragma unroll
            for (int mt = 0; mt < 2; mt++)
                #pragma unroll
                for (int nt = 0; nt < 8; nt++)
                    mma_f16(c[mt][nt], a[mt], b[nt]);
        }
    }

    float* P = Part + (size_t)z * NROI * JS;
    #pragma unroll
    for (int mt = 0; mt < 2; mt++) {
        int row0 = m0 + wm + mt * 16 + g;
        #pragma unroll
        for (int nt = 0; nt < 8; nt++) {
            int j0 = n0 + wn + nt * 8 + tg * 2;
            #pragma unroll
            for (int h = 0; h < 2; h++) {
                int row = row0 + h * 8;
                float2 v = make_float2(c[mt][nt][h*2], c[mt][nt][h*2+1]);
                *reinterpret_cast<float2*>(P + (size_t)row * JS + j0) = v;
            }
        }
    }
}

// reduce: 512 thr, 8 j per thread (2x float4 per z), bias+relu, uint4 fp16 store
template<int J, int JS, int SPLITK>
__global__ void __launch_bounds__(512) reduce_half_kernel(
    const float* __restrict__ Part, const float* __restrict__ bias,
    __half* __restrict__ Cout)
{
    int idx = blockIdx.x * 512 + threadIdx.x;
    if (idx >= NROI * (J / 8)) return;
    int row = idx / (J / 8), jv = idx - row * (J / 8);
    int j = jv * 8;
    float4 v0 = make_float4(0.f, 0.f, 0.f, 0.f);
    float4 v1 = make_float4(0.f, 0.f, 0.f, 0.f);
    #pragma unroll
    for (int z = 0; z < SPLITK; z++) {
        const float* p = Part + ((size_t)z * NROI + row) * JS + j;
        float4 a = *reinterpret_cast<const float4*>(p);
        float4 b = *reinterpret_cast<const float4*>(p + 4);
        v0.x += a.x; v0.y += a.y; v0.z += a.z; v0.w += a.w;
        v1.x += b.x; v1.y += b.y; v1.z += b.z; v1.w += b.w;
    }
    float4 b0 = *reinterpret_cast<const float4*>(bias + j);
    float4 b1 = *reinterpret_cast<const float4*>(bias + j + 4);
    v0.x = fmaxf(v0.x + b0.x, 0.f); v0.y = fmaxf(v0.y + b0.y, 0.f);
    v0.z = fmaxf(v0.z + b0.z, 0.f); v0.w = fmaxf(v0.w + b0.w, 0.f);
    v1.x = fmaxf(v1.x + b1.x, 0.f); v1.y = fmaxf(v1.y + b1.y, 0.f);
    v1.z = fmaxf(v1.z + b1.z, 0.f); v1.w = fmaxf(v1.w + b1.w, 0.f);
    __half2 h0 = __floats2half2_rn(v0.x, v0.y);
    __half2 h1 = __floats2half2_rn(v0.z, v0.w);
    __half2 h2 = __floats2half2_rn(v1.x, v1.y);
    __half2 h3 = __floats2half2_rn(v1.z, v1.w);
    uint4 u;
    u.x = *reinterpret_cast<uint32_t*>(&h0);
    u.y = *reinterpret_cast<uint32_t*>(&h1);
    u.z = *reinterpret_cast<uint32_t*>(&h2);
    u.w = *reinterpret_cast<uint32_t*>(&h3);
    *reinterpret_cast<uint4*>(Cout + (size_t)row * J + j) = u;
}

// ======================= launch =======================
extern "C" void kernel_launch(void* const* d_in, const int* in_sizes, int n_in,
                              void* d_out, int out_size) {
    const float* feat = (const float*)d_in[0];
    const float* rois = (const float*)d_in[1];
    const float* w1   = (const float*)d_in[2];
    const float* b1   = (const float*)d_in[3];
    const float* w2   = (const float*)d_in[4];
    const float* b2   = (const float*)d_in[5];
    const float* w3   = (const float*)d_in[6];
    const float* b3   = (const float*)d_in[7];
    float* out = (float*)d_out;

    static __half *pXh=nullptr, *pH1h=nullptr, *pH2h=nullptr, *pw1h=nullptr, *pw2h=nullptr, *pw3h=nullptr;
    static float *pPart=nullptr;
    static cudaStream_t s2 = nullptr;
    static cudaEvent_t evFork = nullptr, evJoin = nullptr;
    if (!pXh) {
        void* p;
        cudaGetSymbolAddress(&p, g_Xh);   pXh  = (__half*)p;
        cudaGetSymbolAddress(&p, g_H1h);  pH1h = (__half*)p;
        cudaGetSymbolAddress(&p, g_H2h);  pH2h = (__half*)p;
        cudaGetSymbolAddress(&p, g_w1h);  pw1h = (__half*)p;
        cudaGetSymbolAddress(&p, g_w2h);  pw2h = (__half*)p;
        cudaGetSymbolAddress(&p, g_w3h);  pw3h = (__half*)p;
        cudaGetSymbolAddress(&p, g_part); pPart = (float*)p;
        cudaFuncSetAttribute(fcmma_kernel<K1,  DFC, DFC, 9>,
                             cudaFuncAttributeMaxDynamicSharedMemorySize, GEMM_SMEM_BYTES);
        cudaFuncSetAttribute(fcmma_kernel<DFC, DFC, DFC, 8>,
                             cudaFuncAttributeMaxDynamicSharedMemorySize, GEMM_SMEM_BYTES);
        cudaFuncSetAttribute(fcmma_kernel<DFC, M3,  256, FC3_SPLITK>,
                             cudaFuncAttributeMaxDynamicSharedMemorySize, GEMM_SMEM_BYTES);
        cudaFuncSetAttribute(pool_fused_kernel<false>,
                             cudaFuncAttributeMaxDynamicSharedMemorySize, FUSED_SMEM);
        cudaFuncSetAttribute(pool_fused_kernel<true>,
                             cudaFuncAttributeMaxDynamicSharedMemorySize, FUSED_SMEM);
        cudaStreamCreateWithFlags(&s2, cudaStreamNonBlocking);
        cudaEventCreateWithFlags(&evFork, cudaEventDisableTiming);
        cudaEventCreateWithFlags(&evJoin, cudaEventDisableTiming);
    }

    // fork: weight converts on side stream, overlapped with transpose + pool1
    cudaEventRecord(evFork, 0);
    cudaStreamWaitEvent(s2, evFork, 0);
    cvt_half_kernel<<<(DFC*K1/4 + 255)/256, 256, 0, s2>>>(w1, pw1h, DFC*K1/4);
    cvt_half_kernel<<<(DFC*DFC/4 + 255)/256, 256, 0, s2>>>(w2, pw2h, DFC*DFC/4);
    cvt_half_kernel<<<(M3*DFC/4 + 255)/256, 256, 0, s2>>>(w3, pw3h, M3*DFC/4);
    cudaEventRecord(evJoin, s2);

    // main stream: NCHW -> NHWC (fp16, half2 writes), pool1
    dim3 tb(32, 8);
    dim3 tg((HH*WW + 31) / 32, CC / 64, NB);
    transpose_kernel<<<tg, tb>>>(feat);
    pool_fused_kernel<false><<<NROI, 512, FUSED_SMEM>>>(rois, nullptr, nullptr, pXh);

    // join: FC stack needs fp16 weights
    cudaStreamWaitEvent(0, evJoin, 0);

    fcmma_kernel<K1,  DFC, DFC, 9><<<dim3(DFC/BN, NROI/BM, 9), 512, GEMM_SMEM_BYTES>>>(pXh,  pw1h, pPart);
    reduce_half_kernel<DFC, DFC, 9><<<(NROI*DFC/8 + 511)/512, 512>>>(pPart, b1, pH1h);

    fcmma_kernel<DFC, DFC, DFC, 8><<<dim3(DFC/BN, NROI/BM, 8), 512, GEMM_SMEM_BYTES>>>(pH1h, pw2h, pPart);
    reduce_half_kernel<DFC, DFC, 8><<<(NROI*DFC/8 + 511)/512, 512>>>(pPart, b2, pH2h);

    fcmma_kernel<DFC, M3, 256, FC3_SPLITK><<<dim3(1, NROI/BM, FC3_SPLITK), 512, GEMM_SMEM_BYTES>>>(pH2h, pw3h, pPart);

    // fused deformable pool: FC3 reduce + offsets + mask + gather -> out
    pool_fused_kernel<true><<<NROI, 512, FUSED_SMEM>>>(rois, pPart, b3, out);
}

// round 17
// speedup vs baseline: 1.4346x; 1.4346x over previous
#include <cuda_runtime.h>
#include <cuda_fp16.h>
#include <math.h>
#include <stdint.h>

// ---------------- problem constants ----------------
#define NB 2
#define CC 256
#define HH 100
#define WW 100
#define NROI 512
#define PP 7
#define SS 4
#define SCALEF 0.0625f
#define TRANS_STDF 0.1f
#define K1 (CC*PP*PP)     // 12544
#define DFC 1024
#define M3 (PP*PP*3)      // 147

// ---------------- scratch (device globals; no allocs allowed) ----------------
__device__ __half g_featTh[NB*HH*WW*CC];  // NHWC features, fp16 (10.2 MB)
__device__ __half g_Xh[NROI*K1];          // pooled features, fp16
__device__ __half g_H1h[NROI*DFC];
__device__ __half g_H2h[NROI*DFC];
__device__ __half g_w1h[DFC*K1];          // fp16 weights (converted per launch)
__device__ __half g_w2h[DFC*DFC];
__device__ __half g_w3h[M3*DFC];
__device__ float  g_part[9*NROI*DFC];     // split-K partials (fp32)

// ======================= small PTX helpers (sm_80+ baseline only) =======================
__device__ __forceinline__ uint32_t smem_u32(const void* p) {
    uint32_t a;
    asm("{ .reg .u64 t; cvta.to.shared.u64 t, %1; cvt.u32.u64 %0, t; }"
        : "=r"(a) : "l"(p));
    return a;
}

__device__ __forceinline__ void cpasync16(uint32_t dst, const void* src, bool pred) {
    int sz = pred ? 16 : 0;
    asm volatile("cp.async.cg.shared.global [%0], [%1], 16, %2;"
                 :: "r"(dst), "l"(src), "r"(sz) : "memory");
}

__device__ __forceinline__ void mma_f16(float c[4], const uint32_t a[4], const uint32_t b[2]) {
    asm volatile(
        "mma.sync.aligned.m16n8k16.row.col.f32.f16.f16.f32 "
        "{%0,%1,%2,%3}, {%4,%5,%6,%7}, {%8,%9}, {%0,%1,%2,%3};"
        : "+f"(c[0]), "+f"(c[1]), "+f"(c[2]), "+f"(c[3])
        : "r"(a[0]), "r"(a[1]), "r"(a[2]), "r"(a[3]), "r"(b[0]), "r"(b[1]));
}

// ---------------- fused fp32 -> fp16 weight conversion (all 3 weights, 1 launch) ----------------
#define N4_W1 (DFC*K1/4)
#define N4_W2 (DFC*DFC/4)
#define N4_W3 (M3*DFC/4)
#define N4_TOTAL (N4_W1 + N4_W2 + N4_W3)

__global__ void __launch_bounds__(256) cvt_all_kernel(const float* __restrict__ w1,
                                                      const float* __restrict__ w2,
                                                      const float* __restrict__ w3) {
    int i = blockIdx.x * 256 + threadIdx.x;
    if (i >= N4_TOTAL) return;
    const float* src;
    __half* dst;
    int off;
    if (i < N4_W1) {
        src = w1; dst = g_w1h; off = i;
    } else if (i < N4_W1 + N4_W2) {
        src = w2; dst = g_w2h; off = i - N4_W1;
    } else {
        src = w3; dst = g_w3h; off = i - N4_W1 - N4_W2;
    }
    float4 v = reinterpret_cast<const float4*>(src)[off];
    __half2 h0 = __floats2half2_rn(v.x, v.y);
    __half2 h1 = __floats2half2_rn(v.z, v.w);
    reinterpret_cast<__half2*>(dst)[off*2]     = h0;
    reinterpret_cast<__half2*>(dst)[off*2 + 1] = h1;
}

// ---------------- NCHW -> NHWC transpose, fp32 -> fp16 (R15 version) ----------------
__global__ void transpose_kernel(const float* __restrict__ feat) {
    __shared__ float tile[32][33];
    int b   = blockIdx.z;
    int hw0 = blockIdx.x * 32;
    int c0  = blockIdx.y * 32;
    int tx = threadIdx.x, ty = threadIdx.y; // (32, 8)
    const float* src = feat + (size_t)b * CC * HH * WW;
    __half* dst = g_featTh + (size_t)b * HH * WW * CC;
    #pragma unroll
    for (int j = 0; j < 32; j += 8) {
        int c  = c0 + ty + j;
        int hw = hw0 + tx;
        tile[ty + j][tx] = (hw < HH*WW) ? src[c * (HH*WW) + hw] : 0.0f;
    }
    __syncthreads();
    #pragma unroll
    for (int j = 0; j < 32; j += 8) {
        int hw = hw0 + ty + j;
        int c  = c0 + tx;
        if (hw < HH*WW) dst[hw * CC + c] = __float2half_rn(tile[tx][ty + j]);
    }
}

// ================= fused deformable PSROI pool: one block per ROI =================
#define VPITCH 260
#define MROW 56                 // per-bin meta row: [0]=nnz, then (wt, off) pairs (max 25)
#define FC3_SPLITK 32
#define FUSED_SMEM ((49*VPITCH + 49*MROW + 148) * 4)

template<bool TRANS>
__global__ void __launch_bounds__(512) pool_fused_kernel(const float* __restrict__ rois,
                                                         const float* __restrict__ Part,
                                                         const float* __restrict__ bias3,
                                                         void* __restrict__ dstbuf) {
    extern __shared__ float sg[];
    float* vals  = sg;                          // [49 pp][VPITCH]; doubles as stage-1 scratch
    float* smeta = sg + 49*VPITCH;              // [49 pp][MROW]
    float* som   = sg + 49*VPITCH + 49*MROW;    // [147] offsets+mask logits

    int n   = blockIdx.x;
    int tid = threadIdx.x;

    // ---- stage 0: fold FC3 split-K reduce into this kernel ----
    if (TRANS) {
        if (tid < M3) {
            float s = 0.0f;
            #pragma unroll
            for (int z = 0; z < FC3_SPLITK; z++)
                s += Part[((size_t)z * NROI + n) * 256 + tid];
            som[tid] = s + bias3[tid];
        }
        __syncthreads();
    }

    // ---- stage 1: metadata for 49 bins, compacted ----
    if (tid < 49) {
        int pp = tid;
        int ph = pp / 7, pw = pp % 7;
        float* wg = vals + pp * 36;      // scratch (vals not yet live)
        #pragma unroll
        for (int i = 0; i < 36; i++) wg[i] = 0.0f;

        const float* r = rois + n * 5;
        int b = (int)r[0];
        float rsw = rintf(r[1]) * SCALEF - 0.5f;
        float rsh = rintf(r[2]) * SCALEF - 0.5f;
        float rew = (rintf(r[3]) + 1.0f) * SCALEF - 0.5f;
        float reh = (rintf(r[4]) + 1.0f) * SCALEF - 0.5f;
        float roi_w = fmaxf(rew - rsw, 0.1f);
        float roi_h = fmaxf(reh - rsh, 0.1f);
        float bin_h = roi_h / (float)PP;
        float bin_w = roi_w / (float)PP;
        float sub_h = bin_h / (float)SS;
        float sub_w = bin_w / (float)SS;

        float tx_ = 0.0f, ty_ = 0.0f, mask = 1.0f;
        if (TRANS) {
            int part_h = (int)floorf((float)ph / (float)PP * 7.0f);
            int part_w = (int)floorf((float)pw / (float)PP * 7.0f);
            tx_ = som[0*49 + part_h*7 + part_w] * TRANS_STDF;
            ty_ = som[1*49 + part_h*7 + part_w] * TRANS_STDF;
            float ml = som[2*49 + pp];
            mask = 1.0f / (1.0f + expf(-ml));
        }
        float hstart = (float)ph * bin_h + rsh + ty_ * roi_h;
        float wstart = (float)pw * bin_w + rsw + tx_ * roi_w;

        int horg = (int)floorf(fminf(fmaxf(hstart, 0.0f), (float)(HH-1)));
        int worg = (int)floorf(fminf(fmaxf(wstart, 0.0f), (float)(WW-1)));
        int cnt = 0;
        #pragma unroll
        for (int iy = 0; iy < SS; iy++) {
            float h = hstart + (float)iy * sub_h;
            #pragma unroll
            for (int ix = 0; ix < SS; ix++) {
                float w = wstart + (float)ix * sub_w;
                bool valid = (w >= -0.5f) && (w <= (float)WW - 0.5f) &&
                             (h >= -0.5f) && (h <= (float)HH - 0.5f);
                if (!valid) continue;
                cnt++;
                float hc = fminf(fmaxf(h, 0.0f), (float)(HH-1));
                float wc = fminf(fmaxf(w, 0.0f), (float)(WW-1));
                int h0 = (int)floorf(hc), w0 = (int)floorf(wc);
                int h1 = min(h0 + 1, HH - 1), w1 = min(w0 + 1, WW - 1);
                float lh = hc - (float)h0, lw = wc - (float)w0;
                int r0 = min(max(h0 - horg, 0), 5);
                int r1 = min(max(h1 - horg, 0), 5);
                int c0 = min(max(w0 - worg, 0), 5);
                int c1 = min(max(w1 - worg, 0), 5);
                wg[r0*6 + c0] += (1.0f - lh) * (1.0f - lw);
                wg[r0*6 + c1] += (1.0f - lh) * lw;
                wg[r1*6 + c0] += lh * (1.0f - lw);
                wg[r1*6 + c1] += lh * lw;
            }
        }
        float invc = (cnt > 0) ? (1.0f / (float)cnt) : 0.0f;
        float scale = invc * (TRANS ? mask : 1.0f);
        int bbase = b * HH * WW;
        float* m = smeta + pp * MROW;
        int nnz = 0;
        #pragma unroll
        for (int cell = 0; cell < 36; cell++) {
            float wt = wg[cell];
            if (wt != 0.0f) {
                int y = min(horg + cell / 6, HH - 1);
                int x = min(worg + cell % 6, WW - 1);
                m[1 + 2*nnz] = wt * scale;
                m[2 + 2*nnz] = __int_as_float((bbase + y * WW + x) * CC);
                nnz++;
            }
        }
        m[0] = __int_as_float(nnz);
    }
    __syncthreads();

    // ---- stage 2: gather 49 bins x 32 channel-octets (8 halfs each) ----
    #pragma unroll 1
    for (int t = tid; t < 49 * 32; t += 512) {
        int bin = t >> 5;
        int grp = t & 31;
        const float* m = smeta + bin * MROW;
        int nnz = __float_as_int(m[0]);

        float acc[8];
        #pragma unroll
        for (int j = 0; j < 8; j++) acc[j] = 0.0f;
        #pragma unroll 1
        for (int i = 0; i < nnz; i++) {
            float wt  = m[1 + 2*i];
            int   off = __float_as_int(m[2 + 2*i]);
            uint4 f = *reinterpret_cast<const uint4*>(g_featTh + off + grp * 8);
            const __half2* hp = reinterpret_cast<const __half2*>(&f);
            #pragma unroll
            for (int j = 0; j < 4; j++) {
                float2 v = __half22float2(hp[j]);
                acc[2*j]   += wt * v.x;
                acc[2*j+1] += wt * v.y;
            }
        }
        float* vp = vals + bin * VPITCH + grp * 8;
        #pragma unroll
        for (int j = 0; j < 8; j++) vp[j] = acc[j];
    }
    __syncthreads();

    // ---- stage 3: coalesced output in (c*49+pp) layout (guarded: K1 % 512 != 0) ----
    if (TRANS) {
        float* dst = (float*)dstbuf + (size_t)n * K1;
        #pragma unroll 1
        for (int k = tid; k < K1; k += 512) {
            int c = k / 49, pp = k - c * 49;
            dst[k] = vals[pp * VPITCH + c];
        }
    } else {
        __half* dst = (__half*)dstbuf + (size_t)n * K1;
        #pragma unroll 1
        for (int k = tid; k < K1; k += 512) {
            int c = k / 49, pp = k - c * 49;
            dst[k] = __float2half_rn(vals[pp * VPITCH + c]);
        }
    }
}

// ============ FP16 mma.sync GEMM, split-K, BM=128 x BN=256, 16 warps x 32x64 ============
#define BM 128
#define BN 256
#define BK 32
#define HPITCH 40                 // halfs per smem row (conflict-free frag loads)
#define GSTAGES 4
#define ASZH (BM*HPITCH)
#define BSZH (BN*HPITCH)
#define STGH (ASZH+BSZH)
#define GEMM_SMEM_BYTES (GSTAGES*STGH*2)   // 122880 B

template<int KDIM, int JROWS, int JS, int SPLITK>
__global__ void __launch_bounds__(512) fcmma_kernel(
    const __half* __restrict__ A, const __half* __restrict__ Wt,
    float* __restrict__ Part)
{
    static_assert(KDIM % BK == 0, "K multiple of BK");
    constexpr int KT = KDIM / BK;
    constexpr int CH = (KT + SPLITK - 1) / SPLITK;

    extern __shared__ __half smh[];
    int tid  = threadIdx.x;
    int lane = tid & 31, wid = tid >> 5;   // 16 warps
    int m0 = blockIdx.y * BM, n0 = blockIdx.x * BN;
    int z  = blockIdx.z;
    int t0 = z * CH;
    int ntc = min(KT - t0, CH);

    int g = lane >> 2, tg = lane & 3;
    int wm = (wid & 3) * 32;        // 4 warps along M (32 rows each)
    int wn = (wid >> 2) * 64;       // 4 warps along N (64 cols each)

    float c[2][8][4];
    #pragma unroll
    for (int mt = 0; mt < 2; mt++)
        #pragma unroll
        for (int nt = 0; nt < 8; nt++)
            #pragma unroll
            for (int q = 0; q < 4; q++) c[mt][nt][q] = 0.0f;

    int lrow = tid >> 2;     // 0..127
    int lchk = tid & 3;      // 0..3 (16B = 8-half chunks of a BK row)

    auto load_stage = [&](int s, int t) {
        __half* As = smh + s * STGH;
        __half* Bs = As + ASZH;
        int kg = t * BK + lchk * 8;
        cpasync16(smem_u32(As + lrow * HPITCH + lchk * 8),
                  A + (size_t)(m0 + lrow) * KDIM + kg, true);
        #pragma unroll
        for (int it = 0; it < 2; it++) {
            int r = lrow + it * 128;
            int br = n0 + r;
            bool ok = ((JROWS % BN) == 0) || (br < JROWS);
            cpasync16(smem_u32(Bs + r * HPITCH + lchk * 8),
                      Wt + (size_t)(ok ? br : 0) * KDIM + kg, ok);
        }
    };

    #pragma unroll
    for (int s = 0; s < GSTAGES - 1; s++) {
        if (s < ntc) load_stage(s, t0 + s);
        asm volatile("cp.async.commit_group;" ::: "memory");
    }

    #pragma unroll 1
    for (int i = 0; i < ntc; i++) {
        asm volatile("cp.async.wait_group %0;" :: "n"(GSTAGES - 2) : "memory");
        __syncthreads();

        int tn = i + GSTAGES - 1;
        if (tn < ntc) load_stage(tn % GSTAGES, t0 + tn);
        asm volatile("cp.async.commit_group;" ::: "memory");

        const __half* As = smh + (i % GSTAGES) * STGH;
        const __half* Bs = As + ASZH;
        #pragma unroll
        for (int ks = 0; ks < 2; ks++) {
            int kk = ks * 16;
            uint32_t a[2][4], b[8][2];
            #pragma unroll
            for (int mt = 0; mt < 2; mt++) {
                int m = wm + mt * 16 + g;
                a[mt][0] = *reinterpret_cast<const uint32_t*>(As + m * HPITCH + kk + tg*2);
                a[mt][1] = *reinterpret_cast<const uint32_t*>(As + (m + 8) * HPITCH + kk + tg*2);
                a[mt][2] = *reinterpret_cast<const uint32_t*>(As + m * HPITCH + kk + tg*2 + 8);
                a[mt][3] = *reinterpret_cast<const uint32_t*>(As + (m + 8) * HPITCH + kk + tg*2 + 8);
            }
            #pragma unroll
            for (int nt = 0; nt < 8; nt++) {
                int nn = wn + nt * 8 + g;
                b[nt][0] = *reinterpret_cast<const uint32_t*>(Bs + nn * HPITCH + kk + tg*2);
                b[nt][1] = *reinterpret_cast<const uint32_t*>(Bs + nn * HPITCH + kk + tg*2 + 8);
            }
            #pragma unroll
            for (int mt = 0; mt < 2; mt++)
                #pragma unroll
                for (int nt = 0; nt < 8; nt++)
                    mma_f16(c[mt][nt], a[mt], b[nt]);
        }
    }

    float* P = Part + (size_t)z * NROI * JS;
    #pragma unroll
    for (int mt = 0; mt < 2; mt++) {
        int row0 = m0 + wm + mt * 16 + g;
        #pragma unroll
        for (int nt = 0; nt < 8; nt++) {
            int j0 = n0 + wn + nt * 8 + tg * 2;
            #pragma unroll
            for (int h = 0; h < 2; h++) {
                int row = row0 + h * 8;
                float2 v = make_float2(c[mt][nt][h*2], c[mt][nt][h*2+1]);
                *reinterpret_cast<float2*>(P + (size_t)row * JS + j0) = v;
            }
        }
    }
}

// vectorized reduce (R15 version): partials + bias + relu, write fp16 for next GEMM
template<int J, int JS, int SPLITK>
__global__ void __launch_bounds__(256) reduce_half_kernel(
    const float* __restrict__ Part, const float* __restrict__ bias,
    __half* __restrict__ Cout)
{
    int idx = blockIdx.x * 256 + threadIdx.x;
    if (idx >= NROI * (J / 4)) return;
    int row = idx / (J / 4), jv = idx - row * (J / 4);
    int j = jv * 4;
    float4 v = make_float4(0.f, 0.f, 0.f, 0.f);
    #pragma unroll
    for (int z = 0; z < SPLITK; z++) {
        float4 p = *reinterpret_cast<const float4*>(Part + ((size_t)z * NROI + row) * JS + j);
        v.x += p.x; v.y += p.y; v.z += p.z; v.w += p.w;
    }
    float4 bb = *reinterpret_cast<const float4*>(bias + j);
    v.x = fmaxf(v.x + bb.x, 0.f);
    v.y = fmaxf(v.y + bb.y, 0.f);
    v.z = fmaxf(v.z + bb.z, 0.f);
    v.w = fmaxf(v.w + bb.w, 0.f);
    __half2 h0 = __floats2half2_rn(v.x, v.y);
    __half2 h1 = __floats2half2_rn(v.z, v.w);
    uint2 u;
    u.x = *reinterpret_cast<uint32_t*>(&h0);
    u.y = *reinterpret_cast<uint32_t*>(&h1);
    *reinterpret_cast<uint2*>(Cout + (size_t)row * J + j) = u;
}

// ======================= launch =======================
extern "C" void kernel_launch(void* const* d_in, const int* in_sizes, int n_in,
                              void* d_out, int out_size) {
    const float* feat = (const float*)d_in[0];
    const float* rois = (const float*)d_in[1];
    const float* w1   = (const float*)d_in[2];
    const float* b1   = (const float*)d_in[3];
    const float* w2   = (const float*)d_in[4];
    const float* b2   = (const float*)d_in[5];
    const float* w3   = (const float*)d_in[6];
    const float* b3   = (const float*)d_in[7];
    float* out = (float*)d_out;

    static __half *pXh=nullptr, *pH1h=nullptr, *pH2h=nullptr, *pw1h=nullptr, *pw2h=nullptr, *pw3h=nullptr;
    static float *pPart=nullptr;
    static cudaStream_t s2 = nullptr;
    static cudaEvent_t evFork = nullptr, evJoin = nullptr;
    if (!pXh) {
        void* p;
        cudaGetSymbolAddress(&p, g_Xh);   pXh  = (__half*)p;
        cudaGetSymbolAddress(&p, g_H1h);  pH1h = (__half*)p;
        cudaGetSymbolAddress(&p, g_H2h);  pH2h = (__half*)p;
        cudaGetSymbolAddress(&p, g_w1h);  pw1h = (__half*)p;
        cudaGetSymbolAddress(&p, g_w2h);  pw2h = (__half*)p;
        cudaGetSymbolAddress(&p, g_w3h);  pw3h = (__half*)p;
        cudaGetSymbolAddress(&p, g_part); pPart = (float*)p;
        cudaFuncSetAttribute(fcmma_kernel<K1,  DFC, DFC, 9>,
                             cudaFuncAttributeMaxDynamicSharedMemorySize, GEMM_SMEM_BYTES);
        cudaFuncSetAttribute(fcmma_kernel<DFC, DFC, DFC, 8>,
                             cudaFuncAttributeMaxDynamicSharedMemorySize, GEMM_SMEM_BYTES);
        cudaFuncSetAttribute(fcmma_kernel<DFC, M3,  256, FC3_SPLITK>,
                             cudaFuncAttributeMaxDynamicSharedMemorySize, GEMM_SMEM_BYTES);
        cudaFuncSetAttribute(pool_fused_kernel<false>,
                             cudaFuncAttributeMaxDynamicSharedMemorySize, FUSED_SMEM);
        cudaFuncSetAttribute(pool_fused_kernel<true>,
                             cudaFuncAttributeMaxDynamicSharedMemorySize, FUSED_SMEM);
        cudaStreamCreateWithFlags(&s2, cudaStreamNonBlocking);
        cudaEventCreateWithFlags(&evFork, cudaEventDisableTiming);
        cudaEventCreateWithFlags(&evJoin, cudaEventDisableTiming);
    }

    // fork: single fused weight convert on side stream, overlapped with transpose + pool1
    cudaEventRecord(evFork, 0);
    cudaStreamWaitEvent(s2, evFork, 0);
    cvt_all_kernel<<<(N4_TOTAL + 255)/256, 256, 0, s2>>>(w1, w2, w3);
    cudaEventRecord(evJoin, s2);

    // main stream: NCHW -> NHWC (fp16), pool1
    dim3 tb(32, 8);
    dim3 tg((HH*WW + 31) / 32, CC / 32, NB);
    transpose_kernel<<<tg, tb>>>(feat);
    pool_fused_kernel<false><<<NROI, 512, FUSED_SMEM>>>(rois, nullptr, nullptr, pXh);

    // join: FC stack needs fp16 weights
    cudaStreamWaitEvent(0, evJoin, 0);

    fcmma_kernel<K1,  DFC, DFC, 9><<<dim3(DFC/BN, NROI/BM, 9), 512, GEMM_SMEM_BYTES>>>(pXh,  pw1h, pPart);
    reduce_half_kernel<DFC, DFC, 9><<<(NROI*DFC/4 + 255)/256, 256>>>(pPart, b1, pH1h);

    fcmma_kernel<DFC, DFC, DFC, 8><<<dim3(DFC/BN, NROI/BM, 8), 512, GEMM_SMEM_BYTES>>>(pH1h, pw2h, pPart);
    reduce_half_kernel<DFC, DFC, 8><<<(NROI*DFC/4 + 255)/256, 256>>>(pPart, b2, pH2h);

    fcmma_kernel<DFC, M3, 256, FC3_SPLITK><<<dim3(1, NROI/BM, FC3_SPLITK), 512, GEMM_SMEM_BYTES>>>(pH2h, pw3h, pPart);

    // fused deformable pool: FC3 reduce + offsets + mask + gather -> out
    pool_fused_kernel<true><<<NROI, 512, FUSED_SMEM>>>(rois, pPart, b3, out);
}